// round 13
// baseline (speedup 1.0000x reference)
#include <cuda_runtime.h>
#include <cuda_fp16.h>

#define NB 4
#define CIN 256
#define CH 128      // C2
#define NT 16
#define NS 256      // spatial per frame
#define NP 4096     // T*S

typedef unsigned int u32;

// Scratch. Q/M: fp16 pairs [b][p][64 words] (Q pre-scaled by log2e/sqrt(128)).
// Vh: fp16 pairs channel-major [b][c][p/2] (B operand of PV GEMM).
__device__ u32 g_Qh[(size_t)NB*NP*(CH/2)];
__device__ u32 g_Mh[(size_t)NB*NP*(CH/2)];
__device__ u32 g_Vh[(size_t)NB*CH*(NP/2)];

__device__ __forceinline__ u32 smem_u32(const void* p){
    u32 a;
    asm("{ .reg .u64 t; cvta.to.shared.u64 t, %1; cvt.u32.u64 %0, t; }"
        : "=r"(a) : "l"(p));
    return a;
}
__device__ __forceinline__ void cpa16(u32 dst, const void* src){
    asm volatile("cp.async.cg.shared.global [%0], [%1], 16;"
        :: "r"(dst), "l"(src));
}
__device__ __forceinline__ void cpcommit(){
    asm volatile("cp.async.commit_group;" ::: "memory");
}
template<int N> __device__ __forceinline__ void cpwait(){
    asm volatile("cp.async.wait_group %0;" :: "n"(N) : "memory");
}
__device__ __forceinline__ float cvt_tf32(float x){
    u32 r; asm("cvt.rna.tf32.f32 %0, %1;" : "=r"(r) : "f"(x));
    return __uint_as_float(r);
}
__device__ __forceinline__ u32 fb(float x){ return __float_as_uint(x); }
__device__ __forceinline__ float ex2(float x){
    float r; asm("ex2.approx.f32 %0, %1;" : "=f"(r) : "f"(x)); return r;
}
// pack two fp32 -> fp16x2; lo goes to bits[15:0]
__device__ __forceinline__ u32 hfpack(float lo, float hi){
    u32 r; asm("cvt.rn.f16x2.f32 %0, %1, %2;" : "=r"(r) : "f"(hi), "f"(lo));
    return r;
}

// m16n8k8 tf32 mma (proj). Generic sm_80+ PTX.
__device__ __forceinline__ void mma8(float* d, const u32* a, const u32* b){
    asm volatile("mma.sync.aligned.m16n8k8.row.col.f32.tf32.tf32.f32 "
        "{%0,%1,%2,%3}, {%4,%5,%6,%7}, {%8,%9}, {%0,%1,%2,%3};"
        : "+f"(d[0]), "+f"(d[1]), "+f"(d[2]), "+f"(d[3])
        : "r"(a[0]), "r"(a[1]), "r"(a[2]), "r"(a[3]), "r"(b[0]), "r"(b[1]));
}
// m16n8k16 fp16 mma, f32 accum (attention). Generic sm_80+ PTX.
__device__ __forceinline__ void mma16(float* d, const u32* a, const u32* b){
    asm volatile("mma.sync.aligned.m16n8k16.row.col.f32.f16.f16.f32 "
        "{%0,%1,%2,%3}, {%4,%5,%6,%7}, {%8,%9}, {%0,%1,%2,%3};"
        : "+f"(d[0]), "+f"(d[1]), "+f"(d[2]), "+f"(d[3])
        : "r"(a[0]), "r"(a[1]), "r"(a[2]), "r"(a[3]), "r"(b[0]), "r"(b[1]));
}
// ldmatrix x4 (native fp16 fragment loader). Generic sm_75+ PTX.
__device__ __forceinline__ void ldsm4(u32* r, u32 addr){
    asm volatile("ldmatrix.sync.aligned.m8n8.x4.shared.b16 {%0,%1,%2,%3}, [%4];"
        : "=r"(r[0]), "=r"(r[1]), "=r"(r[2]), "=r"(r[3]) : "r"(addr));
}

// ---------------------------------------------------------------------------
// Kernel A: projections, 8 half-chunks (32 c) double-buffered. (r12 version)
// ---------------------------------------------------------------------------
#define PJX 4224
#define PJW 4608
#define PJ_WOFF 8448
#define PROJ_SMEM ((2*PJX + 2*PJW)*4)   // 70656 B

__global__ void __launch_bounds__(256, 2) proj_kernel(
    const float* __restrict__ x,
    const float* __restrict__ Wq,
    const float* __restrict__ Wm,
    const float* __restrict__ Wv,
    float* __restrict__ vout)
{
    extern __shared__ float sm[];
    const u32 sx = smem_u32(sm);
    const u32 sw = smem_u32(sm + PJ_WOFF);

    const int b    = blockIdx.z;
    const int proj = blockIdx.y;
    const int p0   = blockIdx.x * 128;
    const float* W = (proj == 0) ? Wq : ((proj == 1) ? Wm : Wv);

    const int tid = threadIdx.x;
    const int w = tid >> 5, lane = tid & 31;
    const int g = lane >> 2, tt = lane & 3;
    const int m0 = (w >> 1) * 32;
    const int c0 = (w & 1) * 64;

    float acc[2][8][4];
    #pragma unroll
    for (int mi = 0; mi < 2; mi++)
        #pragma unroll
        for (int ni = 0; ni < 8; ni++)
            #pragma unroll
            for (int r = 0; r < 4; r++) acc[mi][ni][r] = 0.f;

    #pragma unroll
    for (int i = 0; i < 4; i++) {
        int idx = i*256 + tid;
        int r = idx >> 5, c4 = (idx & 31) * 4;
        cpa16(sx + (u32)(r*132 + c4)*4,
              x + ((size_t)(b*CIN + r))*NP + p0 + c4);
    }
    #pragma unroll
    for (int i = 0; i < 4; i++) {
        int idx = i*256 + tid;
        int o = idx >> 3, c4 = (idx & 7) * 4;
        cpa16(sw + (u32)(o*36 + c4)*4, W + o*CIN + c4);
    }
    cpcommit();

    for (int ck = 0; ck < 8; ck++) {
        const int buf = ck & 1;
        if (ck < 7) {
            const int nb = buf ^ 1;
            #pragma unroll
            for (int i = 0; i < 4; i++) {
                int idx = i*256 + tid;
                int r = idx >> 5, c4 = (idx & 31) * 4;
                cpa16(sx + (u32)(nb*PJX + r*132 + c4)*4,
                      x + ((size_t)(b*CIN + (ck+1)*32 + r))*NP + p0 + c4);
            }
            #pragma unroll
            for (int i = 0; i < 4; i++) {
                int idx = i*256 + tid;
                int o = idx >> 3, c4 = (idx & 7) * 4;
                cpa16(sw + (u32)(nb*PJW + o*36 + c4)*4,
                      W + o*CIN + (ck+1)*32 + c4);
            }
            cpcommit();
            cpwait<1>();
        } else {
            cpwait<0>();
        }
        __syncthreads();

        const float* xs = sm + buf*PJX;
        const float* ws = sm + PJ_WOFF + buf*PJW;
        #pragma unroll
        for (int k = 0; k < 4; k++) {
            u32 a[2][4], bb[8][2];
            #pragma unroll
            for (int mi = 0; mi < 2; mi++) {
                int p = m0 + mi*16 + g;
                a[mi][0] = fb(cvt_tf32(xs[(k*8+tt)*132 + p]));
                a[mi][1] = fb(cvt_tf32(xs[(k*8+tt)*132 + p + 8]));
                a[mi][2] = fb(cvt_tf32(xs[(k*8+tt+4)*132 + p]));
                a[mi][3] = fb(cvt_tf32(xs[(k*8+tt+4)*132 + p + 8]));
            }
            #pragma unroll
            for (int ni = 0; ni < 8; ni++) {
                int o = c0 + ni*8 + g;
                bb[ni][0] = fb(cvt_tf32(ws[o*36 + k*8 + tt]));
                bb[ni][1] = fb(cvt_tf32(ws[o*36 + k*8 + tt + 4]));
            }
            #pragma unroll
            for (int mi = 0; mi < 2; mi++)
                #pragma unroll
                for (int ni = 0; ni < 8; ni++)
                    mma8(acc[mi][ni], a[mi], bb[ni]);
        }
        __syncthreads();
    }

    if (proj < 2) {
        u32* gdst = proj ? g_Mh : g_Qh;
        const float sc = proj ? 1.0f
                              : 0.08838834764831845f * 1.44269504088896341f;
        #pragma unroll
        for (int mi = 0; mi < 2; mi++) {
            int p = p0 + m0 + mi*16 + g;
            #pragma unroll
            for (int ni = 0; ni < 8; ni++) {
                int pr = (c0 + ni*8) / 2 + tt;
                gdst[((size_t)b*NP + p)*64 + pr] =
                    hfpack(acc[mi][ni][0]*sc, acc[mi][ni][1]*sc);
                gdst[((size_t)b*NP + p + 8)*64 + pr] =
                    hfpack(acc[mi][ni][2]*sc, acc[mi][ni][3]*sc);
            }
        }
    } else {
        #pragma unroll
        for (int mi = 0; mi < 2; mi++) {
            int p = m0 + mi*16 + g;
            #pragma unroll
            for (int ni = 0; ni < 8; ni++) {
                int o = c0 + ni*8 + 2*tt;
                sm[o*132 + p]       = acc[mi][ni][0];
                sm[(o+1)*132 + p]   = acc[mi][ni][1];
                sm[o*132 + p+8]     = acc[mi][ni][2];
                sm[(o+1)*132 + p+8] = acc[mi][ni][3];
            }
        }
        __syncthreads();
        #pragma unroll
        for (int i = 0; i < 16; i++) {
            int idx = i*256 + tid;
            int o = idx >> 5, p4 = (idx & 31) * 4;
            float4 v = *(float4*)&sm[o*132 + p4];
            *(float4*)&vout[((size_t)b*CH + o)*NP + p0 + p4] = v;
            uint2 h;
            h.x = hfpack(v.x, v.y);
            h.y = hfpack(v.z, v.w);
            *(uint2*)&g_Vh[((size_t)b*CH + o)*(NP/2) + (p0 + p4)/2] = h;
        }
    }
}

// ---------------------------------------------------------------------------
// Kernel B: attention, 512 threads (16 warps, 4/SMSP), traffic-neutral split:
// GEMM1 warp tile 32q x 64s (one key-quarter); GEMM2 warp tile 16q x 64c over
// all 256 keys. Same smem layouts as r12; M staged in one shot.
// smem (u32 words): Q[128q][64w] swz @0; M[256s][68w] @8192;
// SS P-pairs [128q][132w] @25600 (fp32 O^T scratch in epilogue);
// V 2 x [128c][36w] @42496; ps[512] @51712; rs[128] @52224.
// ---------------------------------------------------------------------------
#define A_M   8192
#define A_SS  25600
#define A_V   42496
#define A_PS  51712
#define A_RS  52224
#define ATTN_SMEM (52352*4)   // 209408 B
#define VBUF_W 4608           // words per V buffer (128 x 36)

__global__ void __launch_bounds__(512) attn_kernel(float* __restrict__ outR)
{
    extern __shared__ float sm[];
    u32* SS = (u32*)sm + A_SS;
    float* Sf = sm + A_SS;            // epilogue fp32 scratch (aliases SS)
    float* ps = sm + A_PS;
    float* rs = sm + A_RS;
    const u32 sq  = smem_u32(sm);
    const u32 smm = smem_u32((u32*)sm + A_M);
    const u32 ssb = smem_u32((u32*)sm + A_SS);
    const u32 sv  = smem_u32((u32*)sm + A_V);

    const int tid = threadIdx.x;
    const int w = tid >> 5, lane = tid & 31;
    const int g = lane >> 2, tt = lane & 3;
    const int qtile = blockIdx.x, t = blockIdx.y, b = blockIdx.z;
    const int q0 = qtile * 128;

    // GEMM1: 4 q-tiles x 4 key-quarters. GEMM2: 8 q-tiles x 2 c-halves.
    const int m0    = (w >> 2) * 32;   // GEMM1 q tile
    const int sbase = (w & 3) * 64;    // GEMM1 key quarter
    const int m0b   = (w >> 1) * 16;   // GEMM2 q tile
    const int c0    = (w & 1) * 64;    // GEMM2 c half

    const int la7  = lane & 7;
    const int aRow = la7 + ((lane >> 3) & 1) * 8;
    const int aSel = (lane >> 4) & 1;
    const int bRow = la7 + ((lane >> 4) & 1) * 8;
    const int bSel = ((lane >> 3) & 1) * 4;

    const u32* gq = g_Qh + ((size_t)b*NP + q0)*64;
    const u32* gm = g_Mh + ((size_t)b*NP + t*NS)*64;
    const u32* gvh = g_Vh + (size_t)b*CH*(NP/2) + t*(NS/2);

    // ---- G0: Q (swizzled) + all of M ----
    #pragma unroll
    for (int i = 0; i < 4; i++) {
        int idx = i*512 + tid;
        int q = idx >> 4, cs = idx & 15;
        cpa16(sq + (u32)(q*256 + ((cs ^ (q & 7)) * 16)), gq + q*64 + cs*4);
    }
    #pragma unroll
    for (int i = 0; i < 8; i++) {
        int idx = i*512 + tid;
        int s = idx >> 4, cs = idx & 15;
        cpa16(smm + (u32)(s*272 + cs*16), gm + s*64 + cs*4);
    }
    cpcommit();
    // ---- G1, G2: V chunks 0,1 (64 s each, [c][36w] layout) ----
    #pragma unroll
    for (int vj = 0; vj < 2; vj++) {
        #pragma unroll
        for (int i = 0; i < 2; i++) {
            int idx = i*512 + tid;
            int c = idx >> 3, cs = idx & 7;
            cpa16(sv + (u32)(vj*VBUF_W + c*36 + cs*4)*4,
                  gvh + (size_t)c*(NP/2) + vj*32 + cs*4);
        }
        cpcommit();
    }

    float rsum[4] = {0.f, 0.f, 0.f, 0.f};

    u32 qAddrBase[2];
    #pragma unroll
    for (int mi = 0; mi < 2; mi++)
        qAddrBase[mi] = sq + (u32)((m0 + mi*16 + aRow) * 256);

    // ---- GEMM1 (fp16) + fused exp2: 32q x 64s per warp ----
    cpwait<2>();
    __syncthreads();
    {
        float d[2][8][4];
        #pragma unroll
        for (int mi = 0; mi < 2; mi++)
            #pragma unroll
            for (int ni = 0; ni < 8; ni++)
                #pragma unroll
                for (int r = 0; r < 4; r++) d[mi][ni][r] = 0.f;

        u32 mAddr[4];
        #pragma unroll
        for (int p = 0; p < 4; p++)
            mAddr[p] = smm + (u32)(((sbase + p*16 + bRow)*68 + bSel) * 4);

        #pragma unroll
        for (int kk = 0; kk < 8; kk++) {
            u32 a[2][4], bb[4][4];
            const u32 cOff = (u32)((((2*kk + aSel) ^ la7) * 16));
            ldsm4(a[0], qAddrBase[0] + cOff);
            ldsm4(a[1], qAddrBase[1] + cOff);
            #pragma unroll
            for (int p = 0; p < 4; p++) {
                ldsm4(bb[p], mAddr[p]);
                mAddr[p] += 32;
            }
            #pragma unroll
            for (int mi = 0; mi < 2; mi++)
                #pragma unroll
                for (int p = 0; p < 4; p++) {
                    mma16(d[mi][2*p],     a[mi], bb[p]);
                    mma16(d[mi][2*p + 1], a[mi], bb[p] + 2);
                }
        }

        // exp2 on registers, accumulate row-sums, store P (fp16 pairs)
        #pragma unroll
        for (int mi = 0; mi < 2; mi++) {
            int q = m0 + mi*16 + g;
            #pragma unroll
            for (int ni = 0; ni < 8; ni++) {
                int sp = (sbase >> 1) + ni*4 + tt;
                float e0 = ex2(d[mi][ni][0]);
                float e1 = ex2(d[mi][ni][1]);
                float e2 = ex2(d[mi][ni][2]);
                float e3 = ex2(d[mi][ni][3]);
                rsum[mi*2]     += e0 + e1;
                rsum[mi*2 + 1] += e2 + e3;
                SS[q*132 + sp]     = hfpack(e0, e1);
                SS[(q+8)*132 + sp] = hfpack(e2, e3);
            }
        }
    }

    // ---- row-sum: shuffle over tt, 4 quarter-partials, rs = 1/sum ----
    #pragma unroll
    for (int i = 0; i < 4; i++) {
        rsum[i] += __shfl_xor_sync(0xffffffffu, rsum[i], 1);
        rsum[i] += __shfl_xor_sync(0xffffffffu, rsum[i], 2);
    }
    if (tt == 0) {
        ps[(w & 3)*128 + m0 + g]      = rsum[0];
        ps[(w & 3)*128 + m0 + g + 8]  = rsum[1];
        ps[(w & 3)*128 + m0 + 16 + g] = rsum[2];
        ps[(w & 3)*128 + m0 + 24 + g] = rsum[3];
    }
    __syncthreads();   // P + ps visible to all
    if (tid < 128)
        rs[tid] = 1.0f / (ps[tid] + ps[128 + tid] + ps[256 + tid] + ps[384 + tid]);

    // ---- GEMM2 (fp16): 16q x 64c per warp over 4 chunks of 64 s ----
    float e[8][4];
    #pragma unroll
    for (int ni = 0; ni < 8; ni++)
        #pragma unroll
        for (int r = 0; r < 4; r++) e[ni][r] = 0.f;

    const u32 pAddrBase = ssb + (u32)(((m0b + aRow)*132 + aSel*4) * 4);

    #pragma unroll
    for (int j = 0; j < 4; j++) {
        if (j == 3) cpwait<0>(); else cpwait<1>();
        __syncthreads();
        const u32 vb = sv + (u32)((j & 1) * VBUF_W) * 4;

        u32 vAddr[4];
        #pragma unroll
        for (int p = 0; p < 4; p++)
            vAddr[p] = vb + (u32)(((c0 + p*16 + bRow)*36 + bSel) * 4);

        #pragma unroll
        for (int kk = 0; kk < 4; kk++) {
            u32 a[4], bb[4][4];
            const u32 wOff = (u32)((j*32 + kk*8) * 4);
            ldsm4(a, pAddrBase + wOff);
            #pragma unroll
            for (int p = 0; p < 4; p++) {
                ldsm4(bb[p], vAddr[p]);
                vAddr[p] += 32;
            }
            #pragma unroll
            for (int p = 0; p < 4; p++) {
                mma16(e[2*p],     a, bb[p]);
                mma16(e[2*p + 1], a, bb[p] + 2);
            }
        }

        if (j < 2) {
            __syncthreads();
            #pragma unroll
            for (int i = 0; i < 2; i++) {
                int idx = i*512 + tid;
                int c = idx >> 3, cs = idx & 7;
                cpa16(sv + (u32)((j & 1)*VBUF_W + c*36 + cs*4)*4,
                      gvh + (size_t)c*(NP/2) + (j + 2)*32 + cs*4);
            }
            cpcommit();
        } else if (j == 3) {
            __syncthreads();   // all SS reads complete before Sf overwrite
        }
    }

    // ---- epilogue: normalize, transpose via Sf, coalesced writes ----
    {
        int q = m0b + g;
        float rv0 = rs[q], rv1 = rs[q + 8];
        #pragma unroll
        for (int ni = 0; ni < 8; ni++) {
            int c = c0 + ni*8 + 2*tt;
            Sf[c*132 + q]         = e[ni][0] * rv0;
            Sf[(c+1)*132 + q]     = e[ni][1] * rv0;
            Sf[c*132 + q + 8]     = e[ni][2] * rv1;
            Sf[(c+1)*132 + q + 8] = e[ni][3] * rv1;
        }
    }
    __syncthreads();

    const int tq  = qtile >> 1;
    const int hw0 = (qtile & 1) * 128;
    #pragma unroll
    for (int i = 0; i < 8; i++) {
        int idx = i*512 + tid;
        int c = idx >> 5, q4 = (idx & 31) * 4;
        *(float4*)&outR[(((size_t)(b*CH + c)*NT + t)*NT + tq)*NS + hw0 + q4] =
            *(float4*)&Sf[c*132 + q4];
    }
}

// ---------------------------------------------------------------------------
extern "C" void kernel_launch(void* const* d_in, const int* in_sizes, int n_in,
                              void* d_out, int out_size)
{
    const float* x  = (const float*)d_in[0];
    const float* Wq = (const float*)d_in[1];
    const float* Wm = (const float*)d_in[2];
    const float* Wv = (const float*)d_in[3];
    float* out = (float*)d_out;

    const size_t R_SIZE = (size_t)NB * CH * NT * NT * NS;  // 33,554,432
    float* vout = out + R_SIZE;

    cudaFuncSetAttribute(proj_kernel, cudaFuncAttributeMaxDynamicSharedMemorySize, PROJ_SMEM);
    cudaFuncSetAttribute(attn_kernel, cudaFuncAttributeMaxDynamicSharedMemorySize, ATTN_SMEM);

    proj_kernel<<<dim3(32, 3, NB), 256, PROJ_SMEM>>>(x, Wq, Wm, Wv, vout);
    attn_kernel<<<dim3(32, NT, NB), 512, ATTN_SMEM>>>(out);
}

// round 14
// speedup vs baseline: 1.0414x; 1.0414x over previous
#include <cuda_runtime.h>
#include <cuda_fp16.h>

#define NB 4
#define CIN 256
#define CH 128      // C2
#define NT 16
#define NS 256      // spatial per frame
#define NP 4096     // T*S

typedef unsigned int u32;

// Scratch. Q/M: fp16 pairs [b][p][64 words] (Q pre-scaled by log2e/sqrt(128)).
// Vh: fp16 pairs channel-major [b][c][p/2] (B operand of PV GEMM).
__device__ u32 g_Qh[(size_t)NB*NP*(CH/2)];
__device__ u32 g_Mh[(size_t)NB*NP*(CH/2)];
__device__ u32 g_Vh[(size_t)NB*CH*(NP/2)];

__device__ __forceinline__ u32 smem_u32(const void* p){
    u32 a;
    asm("{ .reg .u64 t; cvta.to.shared.u64 t, %1; cvt.u32.u64 %0, t; }"
        : "=r"(a) : "l"(p));
    return a;
}
__device__ __forceinline__ void cpa16(u32 dst, const void* src){
    asm volatile("cp.async.cg.shared.global [%0], [%1], 16;"
        :: "r"(dst), "l"(src));
}
__device__ __forceinline__ void cpcommit(){
    asm volatile("cp.async.commit_group;" ::: "memory");
}
template<int N> __device__ __forceinline__ void cpwait(){
    asm volatile("cp.async.wait_group %0;" :: "n"(N) : "memory");
}
__device__ __forceinline__ float cvt_tf32(float x){
    u32 r; asm("cvt.rna.tf32.f32 %0, %1;" : "=r"(r) : "f"(x));
    return __uint_as_float(r);
}
__device__ __forceinline__ u32 fb(float x){ return __float_as_uint(x); }
__device__ __forceinline__ float ex2(float x){
    float r; asm("ex2.approx.f32 %0, %1;" : "=f"(r) : "f"(x)); return r;
}
// pack two fp32 -> fp16x2; lo goes to bits[15:0]
__device__ __forceinline__ u32 hfpack(float lo, float hi){
    u32 r; asm("cvt.rn.f16x2.f32 %0, %1, %2;" : "=r"(r) : "f"(hi), "f"(lo));
    return r;
}

// m16n8k8 tf32 mma (proj). Generic sm_80+ PTX.
__device__ __forceinline__ void mma8(float* d, const u32* a, const u32* b){
    asm volatile("mma.sync.aligned.m16n8k8.row.col.f32.tf32.tf32.f32 "
        "{%0,%1,%2,%3}, {%4,%5,%6,%7}, {%8,%9}, {%0,%1,%2,%3};"
        : "+f"(d[0]), "+f"(d[1]), "+f"(d[2]), "+f"(d[3])
        : "r"(a[0]), "r"(a[1]), "r"(a[2]), "r"(a[3]), "r"(b[0]), "r"(b[1]));
}
// m16n8k16 fp16 mma, f32 accum (attention). Generic sm_80+ PTX.
__device__ __forceinline__ void mma16(float* d, const u32* a, const u32* b){
    asm volatile("mma.sync.aligned.m16n8k16.row.col.f32.f16.f16.f32 "
        "{%0,%1,%2,%3}, {%4,%5,%6,%7}, {%8,%9}, {%0,%1,%2,%3};"
        : "+f"(d[0]), "+f"(d[1]), "+f"(d[2]), "+f"(d[3])
        : "r"(a[0]), "r"(a[1]), "r"(a[2]), "r"(a[3]), "r"(b[0]), "r"(b[1]));
}
// ldmatrix x4 (native fp16 fragment loader). Generic sm_75+ PTX.
__device__ __forceinline__ void ldsm4(u32* r, u32 addr){
    asm volatile("ldmatrix.sync.aligned.m8n8.x4.shared.b16 {%0,%1,%2,%3}, [%4];"
        : "=r"(r[0]), "=r"(r[1]), "=r"(r[2]), "=r"(r[3]) : "r"(addr));
}

// ---------------------------------------------------------------------------
// Kernel A: projections, 8 half-chunks (32 c) double-buffered. (r12 version)
// ---------------------------------------------------------------------------
#define PJX 4224
#define PJW 4608
#define PJ_WOFF 8448
#define PROJ_SMEM ((2*PJX + 2*PJW)*4)   // 70656 B

__global__ void __launch_bounds__(256, 2) proj_kernel(
    const float* __restrict__ x,
    const float* __restrict__ Wq,
    const float* __restrict__ Wm,
    const float* __restrict__ Wv,
    float* __restrict__ vout)
{
    extern __shared__ float sm[];
    const u32 sx = smem_u32(sm);
    const u32 sw = smem_u32(sm + PJ_WOFF);

    const int b    = blockIdx.z;
    const int proj = blockIdx.y;
    const int p0   = blockIdx.x * 128;
    const float* W = (proj == 0) ? Wq : ((proj == 1) ? Wm : Wv);

    const int tid = threadIdx.x;
    const int w = tid >> 5, lane = tid & 31;
    const int g = lane >> 2, tt = lane & 3;
    const int m0 = (w >> 1) * 32;
    const int c0 = (w & 1) * 64;

    float acc[2][8][4];
    #pragma unroll
    for (int mi = 0; mi < 2; mi++)
        #pragma unroll
        for (int ni = 0; ni < 8; ni++)
            #pragma unroll
            for (int r = 0; r < 4; r++) acc[mi][ni][r] = 0.f;

    #pragma unroll
    for (int i = 0; i < 4; i++) {
        int idx = i*256 + tid;
        int r = idx >> 5, c4 = (idx & 31) * 4;
        cpa16(sx + (u32)(r*132 + c4)*4,
              x + ((size_t)(b*CIN + r))*NP + p0 + c4);
    }
    #pragma unroll
    for (int i = 0; i < 4; i++) {
        int idx = i*256 + tid;
        int o = idx >> 3, c4 = (idx & 7) * 4;
        cpa16(sw + (u32)(o*36 + c4)*4, W + o*CIN + c4);
    }
    cpcommit();

    for (int ck = 0; ck < 8; ck++) {
        const int buf = ck & 1;
        if (ck < 7) {
            const int nb = buf ^ 1;
            #pragma unroll
            for (int i = 0; i < 4; i++) {
                int idx = i*256 + tid;
                int r = idx >> 5, c4 = (idx & 31) * 4;
                cpa16(sx + (u32)(nb*PJX + r*132 + c4)*4,
                      x + ((size_t)(b*CIN + (ck+1)*32 + r))*NP + p0 + c4);
            }
            #pragma unroll
            for (int i = 0; i < 4; i++) {
                int idx = i*256 + tid;
                int o = idx >> 3, c4 = (idx & 7) * 4;
                cpa16(sw + (u32)(nb*PJW + o*36 + c4)*4,
                      W + o*CIN + (ck+1)*32 + c4);
            }
            cpcommit();
            cpwait<1>();
        } else {
            cpwait<0>();
        }
        __syncthreads();

        const float* xs = sm + buf*PJX;
        const float* ws = sm + PJ_WOFF + buf*PJW;
        #pragma unroll
        for (int k = 0; k < 4; k++) {
            u32 a[2][4], bb[8][2];
            #pragma unroll
            for (int mi = 0; mi < 2; mi++) {
                int p = m0 + mi*16 + g;
                a[mi][0] = fb(cvt_tf32(xs[(k*8+tt)*132 + p]));
                a[mi][1] = fb(cvt_tf32(xs[(k*8+tt)*132 + p + 8]));
                a[mi][2] = fb(cvt_tf32(xs[(k*8+tt+4)*132 + p]));
                a[mi][3] = fb(cvt_tf32(xs[(k*8+tt+4)*132 + p + 8]));
            }
            #pragma unroll
            for (int ni = 0; ni < 8; ni++) {
                int o = c0 + ni*8 + g;
                bb[ni][0] = fb(cvt_tf32(ws[o*36 + k*8 + tt]));
                bb[ni][1] = fb(cvt_tf32(ws[o*36 + k*8 + tt + 4]));
            }
            #pragma unroll
            for (int mi = 0; mi < 2; mi++)
                #pragma unroll
                for (int ni = 0; ni < 8; ni++)
                    mma8(acc[mi][ni], a[mi], bb[ni]);
        }
        __syncthreads();
    }

    if (proj < 2) {
        u32* gdst = proj ? g_Mh : g_Qh;
        const float sc = proj ? 1.0f
                              : 0.08838834764831845f * 1.44269504088896341f;
        #pragma unroll
        for (int mi = 0; mi < 2; mi++) {
            int p = p0 + m0 + mi*16 + g;
            #pragma unroll
            for (int ni = 0; ni < 8; ni++) {
                int pr = (c0 + ni*8) / 2 + tt;
                gdst[((size_t)b*NP + p)*64 + pr] =
                    hfpack(acc[mi][ni][0]*sc, acc[mi][ni][1]*sc);
                gdst[((size_t)b*NP + p + 8)*64 + pr] =
                    hfpack(acc[mi][ni][2]*sc, acc[mi][ni][3]*sc);
            }
        }
    } else {
        #pragma unroll
        for (int mi = 0; mi < 2; mi++) {
            int p = m0 + mi*16 + g;
            #pragma unroll
            for (int ni = 0; ni < 8; ni++) {
                int o = c0 + ni*8 + 2*tt;
                sm[o*132 + p]       = acc[mi][ni][0];
                sm[(o+1)*132 + p]   = acc[mi][ni][1];
                sm[o*132 + p+8]     = acc[mi][ni][2];
                sm[(o+1)*132 + p+8] = acc[mi][ni][3];
            }
        }
        __syncthreads();
        #pragma unroll
        for (int i = 0; i < 16; i++) {
            int idx = i*256 + tid;
            int o = idx >> 5, p4 = (idx & 31) * 4;
            float4 v = *(float4*)&sm[o*132 + p4];
            *(float4*)&vout[((size_t)b*CH + o)*NP + p0 + p4] = v;
            uint2 h;
            h.x = hfpack(v.x, v.y);
            h.y = hfpack(v.z, v.w);
            *(uint2*)&g_Vh[((size_t)b*CH + o)*(NP/2) + (p0 + p4)/2] = h;
        }
    }
}

// ---------------------------------------------------------------------------
// Kernel B: attention, 512 threads (16 warps, 4/SMSP).
// GEMM1 warp tile 32q x 64s (key quarters, traffic -256KB vs r12).
// GEMM2 warp tile 32q x 32c over ALL 256 keys (disjoint outputs, no reduce;
// V traffic = r12, P traffic +128KB). Net -128KB at 2x occupancy.
// smem (u32 words): Q[128q][64w] swz @0; M[256s][68w] @8192;
// SS P-pairs [128q][132w] @25600 (fp32 O^T scratch in epilogue);
// V 2 x [128c][36w] @42496; ps[512] @51712; rs[128] @52224.
// ---------------------------------------------------------------------------
#define A_M   8192
#define A_SS  25600
#define A_V   42496
#define A_PS  51712
#define A_RS  52224
#define ATTN_SMEM (52352*4)   // 209408 B
#define VBUF_W 4608           // words per V buffer (128 x 36)

__global__ void __launch_bounds__(512) attn_kernel(float* __restrict__ outR)
{
    extern __shared__ float sm[];
    u32* SS = (u32*)sm + A_SS;
    float* Sf = sm + A_SS;            // epilogue fp32 scratch (aliases SS)
    float* ps = sm + A_PS;
    float* rs = sm + A_RS;
    const u32 sq  = smem_u32(sm);
    const u32 smm = smem_u32((u32*)sm + A_M);
    const u32 ssb = smem_u32((u32*)sm + A_SS);
    const u32 sv  = smem_u32((u32*)sm + A_V);

    const int tid = threadIdx.x;
    const int w = tid >> 5, lane = tid & 31;
    const int g = lane >> 2, tt = lane & 3;
    const int qtile = blockIdx.x, t = blockIdx.y, b = blockIdx.z;
    const int q0 = qtile * 128;

    // GEMM1: 4 q-tiles x 4 key-quarters. GEMM2: 4 q-tiles x 4 c-tiles (32c).
    const int m0    = (w >> 2) * 32;   // q tile (both GEMMs)
    const int sbase = (w & 3) * 64;    // GEMM1 key quarter
    const int c0    = (w & 3) * 32;    // GEMM2 c tile

    const int la7  = lane & 7;
    const int aRow = la7 + ((lane >> 3) & 1) * 8;
    const int aSel = (lane >> 4) & 1;
    const int bRow = la7 + ((lane >> 4) & 1) * 8;
    const int bSel = ((lane >> 3) & 1) * 4;

    const u32* gq = g_Qh + ((size_t)b*NP + q0)*64;
    const u32* gm = g_Mh + ((size_t)b*NP + t*NS)*64;
    const u32* gvh = g_Vh + (size_t)b*CH*(NP/2) + t*(NS/2);

    // ---- G0: Q (swizzled) + all of M ----
    #pragma unroll
    for (int i = 0; i < 4; i++) {
        int idx = i*512 + tid;
        int q = idx >> 4, cs = idx & 15;
        cpa16(sq + (u32)(q*256 + ((cs ^ (q & 7)) * 16)), gq + q*64 + cs*4);
    }
    #pragma unroll
    for (int i = 0; i < 8; i++) {
        int idx = i*512 + tid;
        int s = idx >> 4, cs = idx & 15;
        cpa16(smm + (u32)(s*272 + cs*16), gm + s*64 + cs*4);
    }
    cpcommit();
    // ---- G1, G2: V chunks 0,1 (64 s each, [c][36w] layout) ----
    #pragma unroll
    for (int vj = 0; vj < 2; vj++) {
        #pragma unroll
        for (int i = 0; i < 2; i++) {
            int idx = i*512 + tid;
            int c = idx >> 3, cs = idx & 7;
            cpa16(sv + (u32)(vj*VBUF_W + c*36 + cs*4)*4,
                  gvh + (size_t)c*(NP/2) + vj*32 + cs*4);
        }
        cpcommit();
    }

    float rsum[4] = {0.f, 0.f, 0.f, 0.f};

    u32 qAddrBase[2];
    #pragma unroll
    for (int mi = 0; mi < 2; mi++)
        qAddrBase[mi] = sq + (u32)((m0 + mi*16 + aRow) * 256);

    // ---- GEMM1 (fp16) + fused exp2: 32q x 64s per warp ----
    cpwait<2>();
    __syncthreads();
    {
        float d[2][8][4];
        #pragma unroll
        for (int mi = 0; mi < 2; mi++)
            #pragma unroll
            for (int ni = 0; ni < 8; ni++)
                #pragma unroll
                for (int r = 0; r < 4; r++) d[mi][ni][r] = 0.f;

        u32 mAddr[4];
        #pragma unroll
        for (int p = 0; p < 4; p++)
            mAddr[p] = smm + (u32)(((sbase + p*16 + bRow)*68 + bSel) * 4);

        #pragma unroll
        for (int kk = 0; kk < 8; kk++) {
            u32 a[2][4], bb[4][4];
            const u32 cOff = (u32)((((2*kk + aSel) ^ la7) * 16));
            ldsm4(a[0], qAddrBase[0] + cOff);
            ldsm4(a[1], qAddrBase[1] + cOff);
            #pragma unroll
            for (int p = 0; p < 4; p++) {
                ldsm4(bb[p], mAddr[p]);
                mAddr[p] += 32;
            }
            #pragma unroll
            for (int mi = 0; mi < 2; mi++)
                #pragma unroll
                for (int p = 0; p < 4; p++) {
                    mma16(d[mi][2*p],     a[mi], bb[p]);
                    mma16(d[mi][2*p + 1], a[mi], bb[p] + 2);
                }
        }

        // exp2 on registers, accumulate row-sums, store P (fp16 pairs)
        #pragma unroll
        for (int mi = 0; mi < 2; mi++) {
            int q = m0 + mi*16 + g;
            #pragma unroll
            for (int ni = 0; ni < 8; ni++) {
                int sp = (sbase >> 1) + ni*4 + tt;
                float e0 = ex2(d[mi][ni][0]);
                float e1 = ex2(d[mi][ni][1]);
                float e2 = ex2(d[mi][ni][2]);
                float e3 = ex2(d[mi][ni][3]);
                rsum[mi*2]     += e0 + e1;
                rsum[mi*2 + 1] += e2 + e3;
                SS[q*132 + sp]     = hfpack(e0, e1);
                SS[(q+8)*132 + sp] = hfpack(e2, e3);
            }
        }
    }

    // ---- row-sum: shuffle over tt, 4 quarter-partials, rs = 1/sum ----
    #pragma unroll
    for (int i = 0; i < 4; i++) {
        rsum[i] += __shfl_xor_sync(0xffffffffu, rsum[i], 1);
        rsum[i] += __shfl_xor_sync(0xffffffffu, rsum[i], 2);
    }
    if (tt == 0) {
        ps[(w & 3)*128 + m0 + g]      = rsum[0];
        ps[(w & 3)*128 + m0 + g + 8]  = rsum[1];
        ps[(w & 3)*128 + m0 + 16 + g] = rsum[2];
        ps[(w & 3)*128 + m0 + 24 + g] = rsum[3];
    }
    __syncthreads();   // P + ps visible to all
    if (tid < 128)
        rs[tid] = 1.0f / (ps[tid] + ps[128 + tid] + ps[256 + tid] + ps[384 + tid]);

    // ---- GEMM2 (fp16): 32q x 32c per warp over 4 chunks of 64 s ----
    float e[2][4][4];
    #pragma unroll
    for (int mi = 0; mi < 2; mi++)
        #pragma unroll
        for (int ni = 0; ni < 4; ni++)
            #pragma unroll
            for (int r = 0; r < 4; r++) e[mi][ni][r] = 0.f;

    u32 pAddrBase[2];
    #pragma unroll
    for (int mi = 0; mi < 2; mi++)
        pAddrBase[mi] = ssb + (u32)(((m0 + mi*16 + aRow)*132 + aSel*4) * 4);

    #pragma unroll
    for (int j = 0; j < 4; j++) {
        if (j == 3) cpwait<0>(); else cpwait<1>();
        __syncthreads();
        const u32 vb = sv + (u32)((j & 1) * VBUF_W) * 4;

        u32 vAddr[2];
        #pragma unroll
        for (int p = 0; p < 2; p++)
            vAddr[p] = vb + (u32)(((c0 + p*16 + bRow)*36 + bSel) * 4);

        #pragma unroll
        for (int kk = 0; kk < 4; kk++) {
            u32 a[2][4], bb[2][4];
            const u32 wOff = (u32)((j*32 + kk*8) * 4);
            ldsm4(a[0], pAddrBase[0] + wOff);
            ldsm4(a[1], pAddrBase[1] + wOff);
            #pragma unroll
            for (int p = 0; p < 2; p++) {
                ldsm4(bb[p], vAddr[p]);
                vAddr[p] += 32;
            }
            #pragma unroll
            for (int mi = 0; mi < 2; mi++)
                #pragma unroll
                for (int p = 0; p < 2; p++) {
                    mma16(e[mi][2*p],     a[mi], bb[p]);
                    mma16(e[mi][2*p + 1], a[mi], bb[p] + 2);
                }
        }

        if (j < 2) {
            __syncthreads();
            #pragma unroll
            for (int i = 0; i < 2; i++) {
                int idx = i*512 + tid;
                int c = idx >> 3, cs = idx & 7;
                cpa16(sv + (u32)((j & 1)*VBUF_W + c*36 + cs*4)*4,
                      gvh + (size_t)c*(NP/2) + (j + 2)*32 + cs*4);
            }
            cpcommit();
        } else if (j == 3) {
            __syncthreads();   // all SS reads complete before Sf overwrite
        }
    }

    // ---- epilogue: normalize, transpose via Sf, coalesced writes ----
    #pragma unroll
    for (int mi = 0; mi < 2; mi++) {
        int q = m0 + mi*16 + g;
        float rv0 = rs[q], rv1 = rs[q + 8];
        #pragma unroll
        for (int ni = 0; ni < 4; ni++) {
            int c = c0 + ni*8 + 2*tt;
            Sf[c*132 + q]         = e[mi][ni][0] * rv0;
            Sf[(c+1)*132 + q]     = e[mi][ni][1] * rv0;
            Sf[c*132 + q + 8]     = e[mi][ni][2] * rv1;
            Sf[(c+1)*132 + q + 8] = e[mi][ni][3] * rv1;
        }
    }
    __syncthreads();

    const int tq  = qtile >> 1;
    const int hw0 = (qtile & 1) * 128;
    #pragma unroll
    for (int i = 0; i < 8; i++) {
        int idx = i*512 + tid;
        int c = idx >> 5, q4 = (idx & 31) * 4;
        *(float4*)&outR[(((size_t)(b*CH + c)*NT + t)*NT + tq)*NS + hw0 + q4] =
            *(float4*)&Sf[c*132 + q4];
    }
}

// ---------------------------------------------------------------------------
extern "C" void kernel_launch(void* const* d_in, const int* in_sizes, int n_in,
                              void* d_out, int out_size)
{
    const float* x  = (const float*)d_in[0];
    const float* Wq = (const float*)d_in[1];
    const float* Wm = (const float*)d_in[2];
    const float* Wv = (const float*)d_in[3];
    float* out = (float*)d_out;

    const size_t R_SIZE = (size_t)NB * CH * NT * NT * NS;  // 33,554,432
    float* vout = out + R_SIZE;

    cudaFuncSetAttribute(proj_kernel, cudaFuncAttributeMaxDynamicSharedMemorySize, PROJ_SMEM);
    cudaFuncSetAttribute(attn_kernel, cudaFuncAttributeMaxDynamicSharedMemorySize, ATTN_SMEM);

    proj_kernel<<<dim3(32, 3, NB), 256, PROJ_SMEM>>>(x, Wq, Wm, Wv, vout);
    attn_kernel<<<dim3(32, NT, NB), 512, ATTN_SMEM>>>(out);
}

// round 15
// speedup vs baseline: 1.0962x; 1.0526x over previous
#include <cuda_runtime.h>
#include <cuda_fp16.h>

#define NB 4
#define CIN 256
#define CH 128      // C2
#define NT 16
#define NS 256      // spatial per frame
#define NP 4096     // T*S

typedef unsigned int u32;

// Scratch. Q/M: fp16 pairs [b][p][64 words] (Q pre-scaled by log2e/sqrt(128)).
// Vh: fp16 pairs channel-major [b][c][p/2] (B operand of PV GEMM).
__device__ u32 g_Qh[(size_t)NB*NP*(CH/2)];
__device__ u32 g_Mh[(size_t)NB*NP*(CH/2)];
__device__ u32 g_Vh[(size_t)NB*CH*(NP/2)];

__device__ __forceinline__ u32 smem_u32(const void* p){
    u32 a;
    asm("{ .reg .u64 t; cvta.to.shared.u64 t, %1; cvt.u32.u64 %0, t; }"
        : "=r"(a) : "l"(p));
    return a;
}
__device__ __forceinline__ void cpa16(u32 dst, const void* src){
    asm volatile("cp.async.cg.shared.global [%0], [%1], 16;"
        :: "r"(dst), "l"(src));
}
__device__ __forceinline__ void cpcommit(){
    asm volatile("cp.async.commit_group;" ::: "memory");
}
template<int N> __device__ __forceinline__ void cpwait(){
    asm volatile("cp.async.wait_group %0;" :: "n"(N) : "memory");
}
__device__ __forceinline__ float cvt_tf32(float x){
    u32 r; asm("cvt.rna.tf32.f32 %0, %1;" : "=r"(r) : "f"(x));
    return __uint_as_float(r);
}
__device__ __forceinline__ u32 fb(float x){ return __float_as_uint(x); }
__device__ __forceinline__ float ex2(float x){
    float r; asm("ex2.approx.f32 %0, %1;" : "=f"(r) : "f"(x)); return r;
}
// pack two fp32 -> fp16x2; lo goes to bits[15:0]
__device__ __forceinline__ u32 hfpack(float lo, float hi){
    u32 r; asm("cvt.rn.f16x2.f32 %0, %1, %2;" : "=r"(r) : "f"(hi), "f"(lo));
    return r;
}

// m16n8k8 tf32 mma (proj). Generic sm_80+ PTX.
__device__ __forceinline__ void mma8(float* d, const u32* a, const u32* b){
    asm volatile("mma.sync.aligned.m16n8k8.row.col.f32.tf32.tf32.f32 "
        "{%0,%1,%2,%3}, {%4,%5,%6,%7}, {%8,%9}, {%0,%1,%2,%3};"
        : "+f"(d[0]), "+f"(d[1]), "+f"(d[2]), "+f"(d[3])
        : "r"(a[0]), "r"(a[1]), "r"(a[2]), "r"(a[3]), "r"(b[0]), "r"(b[1]));
}
// m16n8k16 fp16 mma, f32 accum (attention). Generic sm_80+ PTX.
__device__ __forceinline__ void mma16(float* d, const u32* a, const u32* b){
    asm volatile("mma.sync.aligned.m16n8k16.row.col.f32.f16.f16.f32 "
        "{%0,%1,%2,%3}, {%4,%5,%6,%7}, {%8,%9}, {%0,%1,%2,%3};"
        : "+f"(d[0]), "+f"(d[1]), "+f"(d[2]), "+f"(d[3])
        : "r"(a[0]), "r"(a[1]), "r"(a[2]), "r"(a[3]), "r"(b[0]), "r"(b[1]));
}
// ldmatrix x4 (native fp16 fragment loader). Generic sm_75+ PTX.
__device__ __forceinline__ void ldsm4(u32* r, u32 addr){
    asm volatile("ldmatrix.sync.aligned.m8n8.x4.shared.b16 {%0,%1,%2,%3}, [%4];"
        : "=r"(r[0]), "=r"(r[1]), "=r"(r[2]), "=r"(r[3]) : "r"(addr));
}

// ---------------------------------------------------------------------------
// Kernel A (FUSED): all three projections per (ptile, b) CTA. Grid = 128
// CTAs = one wave. x staged ONCE per chunk (shared by Q/M/V); W triple
// per-proj buffers; 8 k-chunks of 32, double-buffered. 512 threads, warp
// tile 32p x 32o (16 warps = 4 p-tiles x 4 o-tiles).
// smem floats: x 2 x [32c][132p] @0; W 2 x 3 x [128o][36c] @8448.
// After compute, smem reused as [128o][132p] fp32 transpose for V output.
// ---------------------------------------------------------------------------
#define PJX 4224          // floats per x buffer (32*132)
#define PJW 4608          // floats per W buffer (128*36)
#define PJ_WOFF 8448      // = 2*PJX
#define PROJ_SMEM ((PJ_WOFF + 6*PJW)*4)   // 144384 B

__global__ void __launch_bounds__(512, 1) proj_kernel(
    const float* __restrict__ x,
    const float* __restrict__ Wq,
    const float* __restrict__ Wm,
    const float* __restrict__ Wv,
    float* __restrict__ vout)
{
    extern __shared__ float sm[];
    const u32 sx = smem_u32(sm);
    const u32 sw = smem_u32(sm + PJ_WOFF);

    const int b  = blockIdx.y;
    const int p0 = blockIdx.x * 128;

    const int tid = threadIdx.x;
    const int w = tid >> 5, lane = tid & 31;
    const int g = lane >> 2, tt = lane & 3;
    const int m0 = (w >> 2) * 32;   // p tile
    const int c0 = (w & 3) * 32;    // o tile

    float acc[3][2][4][4];
    #pragma unroll
    for (int pj = 0; pj < 3; pj++)
        #pragma unroll
        for (int mi = 0; mi < 2; mi++)
            #pragma unroll
            for (int ni = 0; ni < 4; ni++)
                #pragma unroll
                for (int r = 0; r < 4; r++) acc[pj][mi][ni][r] = 0.f;

    // ---- stage chunk 0: x + all three W slices ----
    #pragma unroll
    for (int i = 0; i < 2; i++) {
        int idx = i*512 + tid;
        int r = idx >> 5, c4 = (idx & 31) * 4;
        cpa16(sx + (u32)(r*132 + c4)*4,
              x + ((size_t)(b*CIN + r))*NP + p0 + c4);
    }
    #pragma unroll
    for (int pj = 0; pj < 3; pj++) {
        const float* W = (pj == 0) ? Wq : ((pj == 1) ? Wm : Wv);
        #pragma unroll
        for (int i = 0; i < 2; i++) {
            int idx = i*512 + tid;
            int o = idx >> 3, c4 = (idx & 7) * 4;
            cpa16(sw + (u32)(pj*PJW + o*36 + c4)*4, W + o*CIN + c4);
        }
    }
    cpcommit();

    for (int ck = 0; ck < 8; ck++) {
        const int buf = ck & 1;
        if (ck < 7) {
            const int nb = buf ^ 1;
            #pragma unroll
            for (int i = 0; i < 2; i++) {
                int idx = i*512 + tid;
                int r = idx >> 5, c4 = (idx & 31) * 4;
                cpa16(sx + (u32)(nb*PJX + r*132 + c4)*4,
                      x + ((size_t)(b*CIN + (ck+1)*32 + r))*NP + p0 + c4);
            }
            #pragma unroll
            for (int pj = 0; pj < 3; pj++) {
                const float* W = (pj == 0) ? Wq : ((pj == 1) ? Wm : Wv);
                #pragma unroll
                for (int i = 0; i < 2; i++) {
                    int idx = i*512 + tid;
                    int o = idx >> 3, c4 = (idx & 7) * 4;
                    cpa16(sw + (u32)((nb*3 + pj)*PJW + o*36 + c4)*4,
                          W + o*CIN + (ck+1)*32 + c4);
                }
            }
            cpcommit();
            cpwait<1>();
        } else {
            cpwait<0>();
        }
        __syncthreads();

        const float* xs = sm + buf*PJX;
        #pragma unroll
        for (int k = 0; k < 4; k++) {
            u32 a[2][4];
            #pragma unroll
            for (int mi = 0; mi < 2; mi++) {
                int p = m0 + mi*16 + g;
                a[mi][0] = fb(cvt_tf32(xs[(k*8+tt)*132 + p]));
                a[mi][1] = fb(cvt_tf32(xs[(k*8+tt)*132 + p + 8]));
                a[mi][2] = fb(cvt_tf32(xs[(k*8+tt+4)*132 + p]));
                a[mi][3] = fb(cvt_tf32(xs[(k*8+tt+4)*132 + p + 8]));
            }
            #pragma unroll
            for (int pj = 0; pj < 3; pj++) {
                const float* ws = sm + PJ_WOFF + (buf*3 + pj)*PJW;
                u32 bb[4][2];
                #pragma unroll
                for (int ni = 0; ni < 4; ni++) {
                    int o = c0 + ni*8 + g;
                    bb[ni][0] = fb(cvt_tf32(ws[o*36 + k*8 + tt]));
                    bb[ni][1] = fb(cvt_tf32(ws[o*36 + k*8 + tt + 4]));
                }
                #pragma unroll
                for (int mi = 0; mi < 2; mi++)
                    #pragma unroll
                    for (int ni = 0; ni < 4; ni++)
                        mma8(acc[pj][mi][ni], a[mi], bb[ni]);
            }
        }
        __syncthreads();
    }

    // ---- Q, M: fp16 pairs, position-major ----
    #pragma unroll
    for (int pj = 0; pj < 2; pj++) {
        u32* gdst = pj ? g_Mh : g_Qh;
        // Q pre-scale folds log2(e) so attention uses ex2 directly
        const float sc = pj ? 1.0f
                            : 0.08838834764831845f * 1.44269504088896341f;
        #pragma unroll
        for (int mi = 0; mi < 2; mi++) {
            int p = p0 + m0 + mi*16 + g;
            #pragma unroll
            for (int ni = 0; ni < 4; ni++) {
                int pr = (c0 + ni*8) / 2 + tt;
                gdst[((size_t)b*NP + p)*64 + pr] =
                    hfpack(acc[pj][mi][ni][0]*sc, acc[pj][mi][ni][1]*sc);
                gdst[((size_t)b*NP + p + 8)*64 + pr] =
                    hfpack(acc[pj][mi][ni][2]*sc, acc[pj][mi][ni][3]*sc);
            }
        }
    }

    // ---- V: channel-major via smem transpose; fp32 vout + fp16 g_Vh ----
    // (last chunk's trailing __syncthreads guarantees all smem reads done)
    #pragma unroll
    for (int mi = 0; mi < 2; mi++) {
        int p = m0 + mi*16 + g;
        #pragma unroll
        for (int ni = 0; ni < 4; ni++) {
            int o = c0 + ni*8 + 2*tt;
            sm[o*132 + p]       = acc[2][mi][ni][0];
            sm[(o+1)*132 + p]   = acc[2][mi][ni][1];
            sm[o*132 + p+8]     = acc[2][mi][ni][2];
            sm[(o+1)*132 + p+8] = acc[2][mi][ni][3];
        }
    }
    __syncthreads();
    #pragma unroll
    for (int i = 0; i < 8; i++) {
        int idx = i*512 + tid;
        int o = idx >> 5, p4 = (idx & 31) * 4;
        float4 v = *(float4*)&sm[o*132 + p4];
        *(float4*)&vout[((size_t)b*CH + o)*NP + p0 + p4] = v;
        uint2 h;
        h.x = hfpack(v.x, v.y);
        h.y = hfpack(v.z, v.w);
        *(uint2*)&g_Vh[((size_t)b*CH + o)*(NP/2) + (p0 + p4)/2] = h;
    }
}

// ---------------------------------------------------------------------------
// Kernel B: attention (r12 verbatim — best known: 131.0 us).
// smem (u32 words): Q[128q][64w] swizzled @0; M[256s][68w] @8192;
// SS P-pairs [128q][132w] @25600 (fp32 O^T scratch in epilogue);
// V 2 x [128c][36w] @42496; ps/rs @51712.
// ---------------------------------------------------------------------------
#define A_M   8192
#define A_SS  25600
#define A_V   42496
#define A_PS  51712
#define A_RS  51968
#define ATTN_SMEM (52096*4)   // 208384 B
#define VBUF_W 4608           // words per V buffer (128 x 36)

__global__ void __launch_bounds__(256) attn_kernel(float* __restrict__ outR)
{
    extern __shared__ float sm[];
    u32* SS = (u32*)sm + A_SS;
    float* Sf = sm + A_SS;            // epilogue fp32 scratch (aliases SS)
    float* ps = sm + A_PS;
    float* rs = sm + A_RS;
    const u32 sq  = smem_u32(sm);
    const u32 smm = smem_u32((u32*)sm + A_M);
    const u32 ssb = smem_u32((u32*)sm + A_SS);
    const u32 sv  = smem_u32((u32*)sm + A_V);

    const int tid = threadIdx.x;
    const int w = tid >> 5, lane = tid & 31;
    const int g = lane >> 2, tt = lane & 3;
    const int qtile = blockIdx.x, t = blockIdx.y, b = blockIdx.z;
    const int q0 = qtile * 128;

    const int m0 = (w >> 1) * 32;      // q tile
    const int nh = (w & 1) * 64;       // key half within 128-key group
    const int c0 = (w & 1) * 64;       // c tile (GEMM2)

    const int la7  = lane & 7;
    const int aRow = la7 + ((lane >> 3) & 1) * 8;
    const int aSel = (lane >> 4) & 1;
    const int bRow = la7 + ((lane >> 4) & 1) * 8;
    const int bSel = ((lane >> 3) & 1) * 4;

    const u32* gq = g_Qh + ((size_t)b*NP + q0)*64;
    const u32* gm = g_Mh + ((size_t)b*NP + t*NS)*64;
    const u32* gvh = g_Vh + (size_t)b*CH*(NP/2) + t*(NS/2);

    // ---- G0: Q (swizzled 16B chunks) + M group 0 ----
    #pragma unroll
    for (int i = 0; i < 8; i++) {
        int idx = i*256 + tid;
        int q = idx >> 4, cs = idx & 15;
        cpa16(sq + (u32)(q*256 + ((cs ^ (q & 7)) * 16)), gq + q*64 + cs*4);
    }
    #pragma unroll
    for (int i = 0; i < 8; i++) {
        int idx = i*256 + tid;
        int s = idx >> 4, cs = idx & 15;
        cpa16(smm + (u32)(s*272 + cs*16), gm + s*64 + cs*4);
    }
    cpcommit();
    // ---- G1: M group 1 ----
    #pragma unroll
    for (int i = 0; i < 8; i++) {
        int idx = i*256 + tid;
        int s = idx >> 4, cs = idx & 15;
        cpa16(smm + (u32)((128 + s)*272 + cs*16), gm + (128 + s)*64 + cs*4);
    }
    cpcommit();
    // ---- G2, G3: V chunks 0,1 (64 s each, [c][36w] layout) ----
    #pragma unroll
    for (int vj = 0; vj < 2; vj++) {
        #pragma unroll
        for (int i = 0; i < 4; i++) {
            int idx = i*256 + tid;
            int c = idx >> 3, cs = idx & 7;
            cpa16(sv + (u32)(vj*VBUF_W + c*36 + cs*4)*4,
                  gvh + (size_t)c*(NP/2) + vj*32 + cs*4);
        }
        cpcommit();
    }

    float rsum[4] = {0.f, 0.f, 0.f, 0.f};

    u32 qAddrBase[2];
    #pragma unroll
    for (int mi = 0; mi < 2; mi++)
        qAddrBase[mi] = sq + (u32)((m0 + mi*16 + aRow) * 256);

    // ---- GEMM1 (fp16) + fused exp2, two 128-key groups ----
    #pragma unroll
    for (int j2 = 0; j2 < 2; j2++) {
        if (j2 == 0) cpwait<3>(); else cpwait<2>();
        __syncthreads();

        const int sbase = 128*j2 + nh;
        float d[2][8][4];
        #pragma unroll
        for (int mi = 0; mi < 2; mi++)
            #pragma unroll
            for (int ni = 0; ni < 8; ni++)
                #pragma unroll
                for (int r = 0; r < 4; r++) d[mi][ni][r] = 0.f;

        u32 mAddr[4];
        #pragma unroll
        for (int p = 0; p < 4; p++)
            mAddr[p] = smm + (u32)(((sbase + p*16 + bRow)*68 + bSel) * 4);

        #pragma unroll
        for (int kk = 0; kk < 8; kk++) {
            u32 a[2][4], bb[4][4];
            const u32 cOff = (u32)((((2*kk + aSel) ^ la7) * 16));
            ldsm4(a[0], qAddrBase[0] + cOff);
            ldsm4(a[1], qAddrBase[1] + cOff);
            #pragma unroll
            for (int p = 0; p < 4; p++) {
                ldsm4(bb[p], mAddr[p]);
                mAddr[p] += 32;
            }
            #pragma unroll
            for (int mi = 0; mi < 2; mi++)
                #pragma unroll
                for (int p = 0; p < 4; p++) {
                    mma16(d[mi][2*p],     a[mi], bb[p]);
                    mma16(d[mi][2*p + 1], a[mi], bb[p] + 2);
                }
        }
        // NO barrier here: M groups pre-staged at disjoint addresses; each
        // warp's P region is private until the rowsum barrier.

        // exp2 on registers, accumulate row-sums, store P (fp16 pairs)
        #pragma unroll
        for (int mi = 0; mi < 2; mi++) {
            int q = m0 + mi*16 + g;
            #pragma unroll
            for (int ni = 0; ni < 8; ni++) {
                int sp = (sbase >> 1) + ni*4 + tt;
                float e0 = ex2(d[mi][ni][0]);
                float e1 = ex2(d[mi][ni][1]);
                float e2 = ex2(d[mi][ni][2]);
                float e3 = ex2(d[mi][ni][3]);
                rsum[mi*2]     += e0 + e1;
                rsum[mi*2 + 1] += e2 + e3;
                SS[q*132 + sp]     = hfpack(e0, e1);
                SS[(q+8)*132 + sp] = hfpack(e2, e3);
            }
        }
    }

    // ---- row-sum reduction: shuffle over tt, ps[2][128], rs = 1/sum ----
    #pragma unroll
    for (int i = 0; i < 4; i++) {
        rsum[i] += __shfl_xor_sync(0xffffffffu, rsum[i], 1);
        rsum[i] += __shfl_xor_sync(0xffffffffu, rsum[i], 2);
    }
    if (tt == 0) {
        ps[(w & 1)*128 + m0 + g]      = rsum[0];
        ps[(w & 1)*128 + m0 + g + 8]  = rsum[1];
        ps[(w & 1)*128 + m0 + 16 + g] = rsum[2];
        ps[(w & 1)*128 + m0 + 24 + g] = rsum[3];
    }
    __syncthreads();   // P + ps visible to all
    if (tid < 128) rs[tid] = 1.0f / (ps[tid] + ps[128 + tid]);

    // ---- GEMM2 (fp16): O = P V^T over 4 chunks of 64 s, double-buffered ----
    float e[2][8][4];
    #pragma unroll
    for (int mi = 0; mi < 2; mi++)
        #pragma unroll
        for (int ni = 0; ni < 8; ni++)
            #pragma unroll
            for (int r = 0; r < 4; r++) e[mi][ni][r] = 0.f;

    u32 pAddrBase[2];
    #pragma unroll
    for (int mi = 0; mi < 2; mi++)
        pAddrBase[mi] = ssb + (u32)(((m0 + mi*16 + aRow)*132 + aSel*4) * 4);

    #pragma unroll
    for (int j = 0; j < 4; j++) {
        if (j == 3) cpwait<0>(); else cpwait<1>();
        __syncthreads();
        const u32 vb = sv + (u32)((j & 1) * VBUF_W) * 4;

        u32 vAddr[4];
        #pragma unroll
        for (int p = 0; p < 4; p++)
            vAddr[p] = vb + (u32)(((c0 + p*16 + bRow)*36 + bSel) * 4);

        #pragma unroll
        for (int kk = 0; kk < 4; kk++) {
            u32 a[2][4], bb[4][4];
            const u32 wOff = (u32)((j*32 + kk*8) * 4);
            ldsm4(a[0], pAddrBase[0] + wOff);
            ldsm4(a[1], pAddrBase[1] + wOff);
            #pragma unroll
            for (int p = 0; p < 4; p++) {
                ldsm4(bb[p], vAddr[p]);
                vAddr[p] += 32;
            }
            #pragma unroll
            for (int mi = 0; mi < 2; mi++)
                #pragma unroll
                for (int p = 0; p < 4; p++) {
                    mma16(e[mi][2*p],     a[mi], bb[p]);
                    mma16(e[mi][2*p + 1], a[mi], bb[p] + 2);
                }
        }

        if (j < 2) {
            __syncthreads();
            #pragma unroll
            for (int i = 0; i < 4; i++) {
                int idx = i*256 + tid;
                int c = idx >> 3, cs = idx & 7;
                cpa16(sv + (u32)((j & 1)*VBUF_W + c*36 + cs*4)*4,
                      gvh + (size_t)c*(NP/2) + (j + 2)*32 + cs*4);
            }
            cpcommit();
        } else if (j == 3) {
            __syncthreads();   // all SS reads complete before Sf overwrite
        }
        // j == 2: no barrier needed (next iter waits + syncs before reads)
    }

    // ---- epilogue: normalize, transpose via Sf, coalesced writes ----
    #pragma unroll
    for (int mi = 0; mi < 2; mi++) {
        int q = m0 + mi*16 + g;
        float rv0 = rs[q], rv1 = rs[q + 8];
        #pragma unroll
        for (int ni = 0; ni < 8; ni++) {
            int c = c0 + ni*8 + 2*tt;
            Sf[c*132 + q]         = e[mi][ni][0] * rv0;
            Sf[(c+1)*132 + q]     = e[mi][ni][1] * rv0;
            Sf[c*132 + q + 8]     = e[mi][ni][2] * rv1;
            Sf[(c+1)*132 + q + 8] = e[mi][ni][3] * rv1;
        }
    }
    __syncthreads();

    const int tq  = qtile >> 1;
    const int hw0 = (qtile & 1) * 128;
    #pragma unroll
    for (int i = 0; i < 16; i++) {
        int idx = i*256 + tid;
        int c = idx >> 5, q4 = (idx & 31) * 4;
        *(float4*)&outR[(((size_t)(b*CH + c)*NT + t)*NT + tq)*NS + hw0 + q4] =
            *(float4*)&Sf[c*132 + q4];
    }
}

// ---------------------------------------------------------------------------
extern "C" void kernel_launch(void* const* d_in, const int* in_sizes, int n_in,
                              void* d_out, int out_size)
{
    const float* x  = (const float*)d_in[0];
    const float* Wq = (const float*)d_in[1];
    const float* Wm = (const float*)d_in[2];
    const float* Wv = (const float*)d_in[3];
    float* out = (float*)d_out;

    const size_t R_SIZE = (size_t)NB * CH * NT * NT * NS;  // 33,554,432
    float* vout = out + R_SIZE;

    cudaFuncSetAttribute(proj_kernel, cudaFuncAttributeMaxDynamicSharedMemorySize, PROJ_SMEM);
    cudaFuncSetAttribute(attn_kernel, cudaFuncAttributeMaxDynamicSharedMemorySize, ATTN_SMEM);

    proj_kernel<<<dim3(32, NB), 512, PROJ_SMEM>>>(x, Wq, Wm, Wv, vout);
    attn_kernel<<<dim3(32, NT, NB), 256, ATTN_SMEM>>>(out);
}

// round 17
// speedup vs baseline: 1.1051x; 1.0081x over previous
#include <cuda_runtime.h>
#include <cuda_fp16.h>

#define NB 4
#define CIN 256
#define CH 128      // C2
#define NT 16
#define NS 256      // spatial per frame
#define NP 4096     // T*S

typedef unsigned int u32;

// Scratch. Q/M: fp16 pairs [b][p][64 words] (Q pre-scaled by log2e/sqrt(128)).
// Vh: fp16 pairs channel-major [b][c][p/2] (B operand of PV GEMM).
__device__ u32 g_Qh[(size_t)NB*NP*(CH/2)];
__device__ u32 g_Mh[(size_t)NB*NP*(CH/2)];
__device__ u32 g_Vh[(size_t)NB*CH*(NP/2)];

__device__ __forceinline__ u32 smem_u32(const void* p){
    u32 a;
    asm("{ .reg .u64 t; cvta.to.shared.u64 t, %1; cvt.u32.u64 %0, t; }"
        : "=r"(a) : "l"(p));
    return a;
}
__device__ __forceinline__ void cpa16(u32 dst, const void* src){
    asm volatile("cp.async.cg.shared.global [%0], [%1], 16;"
        :: "r"(dst), "l"(src));
}
__device__ __forceinline__ void cpcommit(){
    asm volatile("cp.async.commit_group;" ::: "memory");
}
template<int N> __device__ __forceinline__ void cpwait(){
    asm volatile("cp.async.wait_group %0;" :: "n"(N) : "memory");
}
__device__ __forceinline__ float cvt_tf32(float x){
    u32 r; asm("cvt.rna.tf32.f32 %0, %1;" : "=r"(r) : "f"(x));
    return __uint_as_float(r);
}
__device__ __forceinline__ u32 fb(float x){ return __float_as_uint(x); }
__device__ __forceinline__ float ex2(float x){
    float r; asm("ex2.approx.f32 %0, %1;" : "=f"(r) : "f"(x)); return r;
}
// pack two fp32 -> fp16x2; lo goes to bits[15:0]
__device__ __forceinline__ u32 hfpack(float lo, float hi){
    u32 r; asm("cvt.rn.f16x2.f32 %0, %1, %2;" : "=r"(r) : "f"(hi), "f"(lo));
    return r;
}

// m16n8k8 tf32 mma (proj). Generic sm_80+ PTX.
__device__ __forceinline__ void mma8(float* d, const u32* a, const u32* b){
    asm volatile("mma.sync.aligned.m16n8k8.row.col.f32.tf32.tf32.f32 "
        "{%0,%1,%2,%3}, {%4,%5,%6,%7}, {%8,%9}, {%0,%1,%2,%3};"
        : "+f"(d[0]), "+f"(d[1]), "+f"(d[2]), "+f"(d[3])
        : "r"(a[0]), "r"(a[1]), "r"(a[2]), "r"(a[3]), "r"(b[0]), "r"(b[1]));
}
// m16n8k16 fp16 mma, f32 accum (attention). Generic sm_80+ PTX.
__device__ __forceinline__ void mma16(float* d, const u32* a, const u32* b){
    asm volatile("mma.sync.aligned.m16n8k16.row.col.f32.f16.f16.f32 "
        "{%0,%1,%2,%3}, {%4,%5,%6,%7}, {%8,%9}, {%0,%1,%2,%3};"
        : "+f"(d[0]), "+f"(d[1]), "+f"(d[2]), "+f"(d[3])
        : "r"(a[0]), "r"(a[1]), "r"(a[2]), "r"(a[3]), "r"(b[0]), "r"(b[1]));
}
// ldmatrix x4 (native fp16 fragment loader). Generic sm_75+ PTX.
__device__ __forceinline__ void ldsm4(u32* r, u32 addr){
    asm volatile("ldmatrix.sync.aligned.m8n8.x4.shared.b16 {%0,%1,%2,%3}, [%4];"
        : "=r"(r[0]), "=r"(r[1]), "=r"(r[2]), "=r"(r[3]) : "r"(addr));
}

// ---------------------------------------------------------------------------
// Kernel A (FUSED, r15): all three projections per (ptile, b) CTA.
// ---------------------------------------------------------------------------
#define PJX 4224
#define PJW 4608
#define PJ_WOFF 8448
#define PROJ_SMEM ((PJ_WOFF + 6*PJW)*4)   // 144384 B

__global__ void __launch_bounds__(512, 1) proj_kernel(
    const float* __restrict__ x,
    const float* __restrict__ Wq,
    const float* __restrict__ Wm,
    const float* __restrict__ Wv,
    float* __restrict__ vout)
{
    extern __shared__ float sm[];
    const u32 sx = smem_u32(sm);
    const u32 sw = smem_u32(sm + PJ_WOFF);

    const int b  = blockIdx.y;
    const int p0 = blockIdx.x * 128;

    const int tid = threadIdx.x;
    const int w = tid >> 5, lane = tid & 31;
    const int g = lane >> 2, tt = lane & 3;
    const int m0 = (w >> 2) * 32;   // p tile
    const int c0 = (w & 3) * 32;    // o tile

    float acc[3][2][4][4];
    #pragma unroll
    for (int pj = 0; pj < 3; pj++)
        #pragma unroll
        for (int mi = 0; mi < 2; mi++)
            #pragma unroll
            for (int ni = 0; ni < 4; ni++)
                #pragma unroll
                for (int r = 0; r < 4; r++) acc[pj][mi][ni][r] = 0.f;

    #pragma unroll
    for (int i = 0; i < 2; i++) {
        int idx = i*512 + tid;
        int r = idx >> 5, c4 = (idx & 31) * 4;
        cpa16(sx + (u32)(r*132 + c4)*4,
              x + ((size_t)(b*CIN + r))*NP + p0 + c4);
    }
    #pragma unroll
    for (int pj = 0; pj < 3; pj++) {
        const float* W = (pj == 0) ? Wq : ((pj == 1) ? Wm : Wv);
        #pragma unroll
        for (int i = 0; i < 2; i++) {
            int idx = i*512 + tid;
            int o = idx >> 3, c4 = (idx & 7) * 4;
            cpa16(sw + (u32)(pj*PJW + o*36 + c4)*4, W + o*CIN + c4);
        }
    }
    cpcommit();

    for (int ck = 0; ck < 8; ck++) {
        const int buf = ck & 1;
        if (ck < 7) {
            const int nb = buf ^ 1;
            #pragma unroll
            for (int i = 0; i < 2; i++) {
                int idx = i*512 + tid;
                int r = idx >> 5, c4 = (idx & 31) * 4;
                cpa16(sx + (u32)(nb*PJX + r*132 + c4)*4,
                      x + ((size_t)(b*CIN + (ck+1)*32 + r))*NP + p0 + c4);
            }
            #pragma unroll
            for (int pj = 0; pj < 3; pj++) {
                const float* W = (pj == 0) ? Wq : ((pj == 1) ? Wm : Wv);
                #pragma unroll
                for (int i = 0; i < 2; i++) {
                    int idx = i*512 + tid;
                    int o = idx >> 3, c4 = (idx & 7) * 4;
                    cpa16(sw + (u32)((nb*3 + pj)*PJW + o*36 + c4)*4,
                          W + o*CIN + (ck+1)*32 + c4);
                }
            }
            cpcommit();
            cpwait<1>();
        } else {
            cpwait<0>();
        }
        __syncthreads();

        const float* xs = sm + buf*PJX;
        #pragma unroll
        for (int k = 0; k < 4; k++) {
            u32 a[2][4];
            #pragma unroll
            for (int mi = 0; mi < 2; mi++) {
                int p = m0 + mi*16 + g;
                a[mi][0] = fb(cvt_tf32(xs[(k*8+tt)*132 + p]));
                a[mi][1] = fb(cvt_tf32(xs[(k*8+tt)*132 + p + 8]));
                a[mi][2] = fb(cvt_tf32(xs[(k*8+tt+4)*132 + p]));
                a[mi][3] = fb(cvt_tf32(xs[(k*8+tt+4)*132 + p + 8]));
            }
            #pragma unroll
            for (int pj = 0; pj < 3; pj++) {
                const float* ws = sm + PJ_WOFF + (buf*3 + pj)*PJW;
                u32 bb[4][2];
                #pragma unroll
                for (int ni = 0; ni < 4; ni++) {
                    int o = c0 + ni*8 + g;
                    bb[ni][0] = fb(cvt_tf32(ws[o*36 + k*8 + tt]));
                    bb[ni][1] = fb(cvt_tf32(ws[o*36 + k*8 + tt + 4]));
                }
                #pragma unroll
                for (int mi = 0; mi < 2; mi++)
                    #pragma unroll
                    for (int ni = 0; ni < 4; ni++)
                        mma8(acc[pj][mi][ni], a[mi], bb[ni]);
            }
        }
        __syncthreads();
    }

    // ---- Q, M: fp16 pairs, position-major ----
    #pragma unroll
    for (int pj = 0; pj < 2; pj++) {
        u32* gdst = pj ? g_Mh : g_Qh;
        const float sc = pj ? 1.0f
                            : 0.08838834764831845f * 1.44269504088896341f;
        #pragma unroll
        for (int mi = 0; mi < 2; mi++) {
            int p = p0 + m0 + mi*16 + g;
            #pragma unroll
            for (int ni = 0; ni < 4; ni++) {
                int pr = (c0 + ni*8) / 2 + tt;
                gdst[((size_t)b*NP + p)*64 + pr] =
                    hfpack(acc[pj][mi][ni][0]*sc, acc[pj][mi][ni][1]*sc);
                gdst[((size_t)b*NP + p + 8)*64 + pr] =
                    hfpack(acc[pj][mi][ni][2]*sc, acc[pj][mi][ni][3]*sc);
            }
        }
    }

    // ---- V: channel-major via smem transpose; fp32 vout + fp16 g_Vh ----
    #pragma unroll
    for (int mi = 0; mi < 2; mi++) {
        int p = m0 + mi*16 + g;
        #pragma unroll
        for (int ni = 0; ni < 4; ni++) {
            int o = c0 + ni*8 + 2*tt;
            sm[o*132 + p]       = acc[2][mi][ni][0];
            sm[(o+1)*132 + p]   = acc[2][mi][ni][1];
            sm[o*132 + p+8]     = acc[2][mi][ni][2];
            sm[(o+1)*132 + p+8] = acc[2][mi][ni][3];
        }
    }
    __syncthreads();
    #pragma unroll
    for (int i = 0; i < 8; i++) {
        int idx = i*512 + tid;
        int o = idx >> 5, p4 = (idx & 31) * 4;
        float4 v = *(float4*)&sm[o*132 + p4];
        *(float4*)&vout[((size_t)b*CH + o)*NP + p0 + p4] = v;
        uint2 h;
        h.x = hfpack(v.x, v.y);
        h.y = hfpack(v.z, v.w);
        *(uint2*)&g_Vh[((size_t)b*CH + o)*(NP/2) + (p0 + p4)/2] = h;
    }
}

// ---------------------------------------------------------------------------
// Kernel B: attention, key-quartered, 107.0 KB smem -> 2 CTAs/SM.
// Per 64-key quarter: GEMM1 (warp 32q x 32s) -> exp2 -> P [128q][36w] ->
// GEMM2 (warp 32q x 64c, unnormalized accumulate).
// V DOUBLE-buffered (r16 bug: single V buffer raced with its own prefetch).
// M single buffer (M_{j+1} issued after MID_j barrier; reads end at GEMM1_j).
// smem (u32 words): Q[128q][64w] swz @0; M[64s][68w] @8192;
// V 2 x [128c][36w] @12544; P[128q][36w] @21760; ps[256] @26368; rs @26624.
// ---------------------------------------------------------------------------
#define A_M   8192
#define A_V   12544
#define A_P   21760
#define A_PS  26368
#define A_RS  26624
#define ATTN_SMEM (26752*4)   // 107008 B
#define VBUF_W 4608           // words per V buffer (128 x 36)

__global__ void __launch_bounds__(256, 2) attn_kernel(float* __restrict__ outR)
{
    extern __shared__ float sm[];
    u32* SS = (u32*)sm + A_P;
    float* ps = sm + A_PS;
    float* rs = sm + A_RS;
    const u32 sq  = smem_u32(sm);
    const u32 smm = smem_u32((u32*)sm + A_M);
    const u32 sv  = smem_u32((u32*)sm + A_V);
    const u32 ssp = smem_u32((u32*)sm + A_P);

    const int tid = threadIdx.x;
    const int w = tid >> 5, lane = tid & 31;
    const int g = lane >> 2, tt = lane & 3;
    const int qtile = blockIdx.x, t = blockIdx.y, b = blockIdx.z;
    const int q0 = qtile * 128;

    const int m0 = (w >> 1) * 32;      // q tile (both GEMMs)
    const int nq = (w & 1);            // GEMM1: 32-s half of quarter
    const int c0 = (w & 1) * 64;       // GEMM2 c tile

    const int la7  = lane & 7;
    const int aRow = la7 + ((lane >> 3) & 1) * 8;
    const int aSel = (lane >> 4) & 1;
    const int bRow = la7 + ((lane >> 4) & 1) * 8;
    const int bSel = ((lane >> 3) & 1) * 4;

    const u32* gq = g_Qh + ((size_t)b*NP + q0)*64;
    const u32* gm = g_Mh + ((size_t)b*NP + t*NS)*64;
    const u32* gvh = g_Vh + (size_t)b*CH*(NP/2) + t*(NS/2);

    // ---- C0: Q (swizzled) + M quarter 0 ----
    #pragma unroll
    for (int i = 0; i < 8; i++) {
        int idx = i*256 + tid;
        int q = idx >> 4, cs = idx & 15;
        cpa16(sq + (u32)(q*256 + ((cs ^ (q & 7)) * 16)), gq + q*64 + cs*4);
    }
    #pragma unroll
    for (int i = 0; i < 4; i++) {
        int idx = i*256 + tid;
        int s = idx >> 4, cs = idx & 15;
        cpa16(smm + (u32)(s*272 + cs*16), gm + s*64 + cs*4);
    }
    cpcommit();
    // ---- C1: V quarter 0 -> vbuf[0] ----
    #pragma unroll
    for (int i = 0; i < 4; i++) {
        int idx = i*256 + tid;
        int c = idx >> 3, cs = idx & 7;
        cpa16(sv + (u32)(c*36 + cs*4)*4, gvh + (size_t)c*(NP/2) + cs*4);
    }
    cpcommit();

    float rsum[4] = {0.f, 0.f, 0.f, 0.f};
    float e[2][8][4];
    #pragma unroll
    for (int mi = 0; mi < 2; mi++)
        #pragma unroll
        for (int ni = 0; ni < 8; ni++)
            #pragma unroll
            for (int r = 0; r < 4; r++) e[mi][ni][r] = 0.f;

    u32 qAddrBase[2], pAddrBase[2];
    #pragma unroll
    for (int mi = 0; mi < 2; mi++) {
        qAddrBase[mi] = sq  + (u32)((m0 + mi*16 + aRow) * 256);
        pAddrBase[mi] = ssp + (u32)(((m0 + mi*16 + aRow)*36 + aSel*4) * 4);
    }

    #pragma unroll
    for (int j = 0; j < 4; j++) {
        // ---- TOP_j: M_j ready ----
        // j=0: drain C0 {Q,M0}, leave {V0}. j>=1: drain {V_j, M_j}.
        if (j == 0) cpwait<1>(); else cpwait<0>();
        __syncthreads();
        // prefetch V_{j+1} into the OTHER V buffer (its last reader was
        // GEMM2_{j-1}, which completed before this barrier)
        if (j < 3) {
            const u32 vdst = sv + (u32)(((j + 1) & 1) * VBUF_W) * 4;
            #pragma unroll
            for (int i = 0; i < 4; i++) {
                int idx = i*256 + tid;
                int c = idx >> 3, cs = idx & 7;
                cpa16(vdst + (u32)(c*36 + cs*4)*4,
                      gvh + (size_t)c*(NP/2) + (j+1)*32 + cs*4);
            }
            cpcommit();
        }

        // ---- GEMM1 (fp16): S quarter, warp tile 32q x 32s ----
        float d[2][4][4];
        #pragma unroll
        for (int mi = 0; mi < 2; mi++)
            #pragma unroll
            for (int ni = 0; ni < 4; ni++)
                #pragma unroll
                for (int r = 0; r < 4; r++) d[mi][ni][r] = 0.f;

        u32 mAddr[2];
        #pragma unroll
        for (int p = 0; p < 2; p++)
            mAddr[p] = smm + (u32)(((nq*32 + p*16 + bRow)*68 + bSel) * 4);

        #pragma unroll
        for (int kk = 0; kk < 8; kk++) {
            u32 a[2][4], bb[2][4];
            const u32 cOff = (u32)((((2*kk + aSel) ^ la7) * 16));
            ldsm4(a[0], qAddrBase[0] + cOff);
            ldsm4(a[1], qAddrBase[1] + cOff);
            #pragma unroll
            for (int p = 0; p < 2; p++) {
                ldsm4(bb[p], mAddr[p]);
                mAddr[p] += 32;
            }
            #pragma unroll
            for (int mi = 0; mi < 2; mi++)
                #pragma unroll
                for (int p = 0; p < 2; p++) {
                    mma16(d[mi][2*p],     a[mi], bb[p]);
                    mma16(d[mi][2*p + 1], a[mi], bb[p] + 2);
                }
        }

        // ---- exp2, rowsum accumulate, store P quarter (fp16 pairs) ----
        #pragma unroll
        for (int mi = 0; mi < 2; mi++) {
            int q = m0 + mi*16 + g;
            #pragma unroll
            for (int ni = 0; ni < 4; ni++) {
                int sp = nq*16 + ni*4 + tt;
                float e0 = ex2(d[mi][ni][0]);
                float e1 = ex2(d[mi][ni][1]);
                float e2 = ex2(d[mi][ni][2]);
                float e3 = ex2(d[mi][ni][3]);
                rsum[mi*2]     += e0 + e1;
                rsum[mi*2 + 1] += e2 + e3;
                SS[q*36 + sp]     = hfpack(e0, e1);
                SS[(q+8)*36 + sp] = hfpack(e2, e3);
            }
        }
        if (j == 3) {   // final rowsum partials
            #pragma unroll
            for (int i = 0; i < 4; i++) {
                rsum[i] += __shfl_xor_sync(0xffffffffu, rsum[i], 1);
                rsum[i] += __shfl_xor_sync(0xffffffffu, rsum[i], 2);
            }
            if (tt == 0) {
                ps[nq*128 + m0 + g]      = rsum[0];
                ps[nq*128 + m0 + g + 8]  = rsum[1];
                ps[nq*128 + m0 + 16 + g] = rsum[2];
                ps[nq*128 + m0 + 24 + g] = rsum[3];
            }
        }

        // ---- MID_j: V_j ready, P_j visible, M buffer free ----
        // j=0: drain {V0}, leave {V1}. j>=1: V_j already drained at TOP_j;
        // leave {V_{j+1}} pending (j=3: nothing pending).
        cpwait<1>();
        __syncthreads();
        if (j == 3 && tid < 128)
            rs[tid] = 1.0f / (ps[tid] + ps[128 + tid]);
        // prefetch M_{j+1} (reads of M_j ended at GEMM1_j, before barrier)
        if (j < 3) {
            #pragma unroll
            for (int i = 0; i < 4; i++) {
                int idx = i*256 + tid;
                int s = idx >> 4, cs = idx & 15;
                cpa16(smm + (u32)(s*272 + cs*16),
                      gm + (size_t)((j+1)*64 + s)*64 + cs*4);
            }
            cpcommit();
        }

        // ---- GEMM2 (fp16): e += P_j * V_j (warp 32q x 64c, 4 k-steps) ----
        const u32 vb = sv + (u32)((j & 1) * VBUF_W) * 4;
        u32 vAddr[4];
        #pragma unroll
        for (int p = 0; p < 4; p++)
            vAddr[p] = vb + (u32)(((c0 + p*16 + bRow)*36 + bSel) * 4);

        #pragma unroll
        for (int kk = 0; kk < 4; kk++) {
            u32 a[2][4], bb[4][4];
            const u32 wOff = (u32)(kk * 32);
            ldsm4(a[0], pAddrBase[0] + wOff);
            ldsm4(a[1], pAddrBase[1] + wOff);
            #pragma unroll
            for (int p = 0; p < 4; p++) {
                ldsm4(bb[p], vAddr[p]);
                vAddr[p] += 32;
            }
            #pragma unroll
            for (int mi = 0; mi < 2; mi++)
                #pragma unroll
                for (int p = 0; p < 4; p++) {
                    mma16(e[mi][2*p],     a[mi], bb[p]);
                    mma16(e[mi][2*p + 1], a[mi], bb[p] + 2);
                }
        }
    }

    __syncthreads();   // rs visible; all P/V reads complete

    // ---- epilogue: normalize, direct register->gmem stores ----
    const int tq  = qtile >> 1;
    const int hw0 = (qtile & 1) * 128;
    #pragma unroll
    for (int mi = 0; mi < 2; mi++) {
        int q = m0 + mi*16 + g;
        float rv0 = rs[q], rv1 = rs[q + 8];
        #pragma unroll
        for (int ni = 0; ni < 8; ni++) {
            int c = c0 + ni*8 + 2*tt;
            float* b0 = outR + (((size_t)(b*CH + c)*NT + t)*NT + tq)*NS + hw0;
            float* b1 = outR + (((size_t)(b*CH + c + 1)*NT + t)*NT + tq)*NS + hw0;
            b0[q]     = e[mi][ni][0] * rv0;
            b1[q]     = e[mi][ni][1] * rv0;
            b0[q + 8] = e[mi][ni][2] * rv1;
            b1[q + 8] = e[mi][ni][3] * rv1;
        }
    }
}

// ---------------------------------------------------------------------------
extern "C" void kernel_launch(void* const* d_in, const int* in_sizes, int n_in,
                              void* d_out, int out_size)
{
    const float* x  = (const float*)d_in[0];
    const float* Wq = (const float*)d_in[1];
    const float* Wm = (const float*)d_in[2];
    const float* Wv = (const float*)d_in[3];
    float* out = (float*)d_out;

    const size_t R_SIZE = (size_t)NB * CH * NT * NT * NS;  // 33,554,432
    float* vout = out + R_SIZE;

    cudaFuncSetAttribute(proj_kernel, cudaFuncAttributeMaxDynamicSharedMemorySize, PROJ_SMEM);
    cudaFuncSetAttribute(attn_kernel, cudaFuncAttributeMaxDynamicSharedMemorySize, ATTN_SMEM);

    proj_kernel<<<dim3(32, NB), 512, PROJ_SMEM>>>(x, Wq, Wm, Wv, vout);
    attn_kernel<<<dim3(32, NT, NB), 256, ATTN_SMEM>>>(out);
}